// round 8
// baseline (speedup 1.0000x reference)
#include <cuda_runtime.h>
#include <cuda_bf16.h>

// Problem constants (fixed by setup_inputs: N=50000, E=800000, D=100, 2 layers)
#define NMAX 50000
#define EMAX 800000
#define DD   100
#define C4   25      // D/4 float4 chunks per dense fp32 row (feat / output)
#define CP   32      // pitched float4 chunks per fp32 internal row (512B)
#define B2P  32      // uint2 (4 bf16) chunks per bf16 row (256B, line-aligned)
#define WPITCH 104   // padded pitch (floats) for transposed W rows

typedef unsigned long long u64;

// ---- static device scratch (no runtime allocation allowed) ----
__device__ uint2 g_bufA[NMAX * B2P];       // GEMM output in bf16 (SpMM gather source)
__device__ float g_bufB[NMAX * CP * 4];    // layer-0 SpMM output x1 (fp32, GEMM1 input)
__device__ uint2 g_bufC[NMAX * B2P];       // layer-1 SpMM output x2 (bf16, finale only)
__device__ float g_Wt[2 * DD * WPITCH];    // k-major transposed weights
__device__ int   g_cnt[NMAX];              // per-row edge counts
__device__ int   g_rowptr[NMAX + 1];       // CSR row pointers
__device__ float g_deginv[NMAX];           // 1/(cnt+1)  (self loop included)
__device__ int   g_col[EMAX];              // CSR column (src) indices
__device__ int   g_rank[EMAX];             // per-edge rank within its dst row
__device__ float g_sfac[2 * NMAX];         // per-row 1/max(norm,eps) per layer

// ---------------- f32x2 helpers ----------------
__device__ __forceinline__ u64 dup2(float a) {
    u64 r; unsigned ai = __float_as_uint(a);
    asm("mov.b64 %0, {%1, %1};" : "=l"(r) : "r"(ai));
    return r;
}
__device__ __forceinline__ void ffma2(u64& acc, u64 a, u64 b) {
    asm("fma.rn.f32x2 %0, %1, %2, %0;" : "+l"(acc) : "l"(a), "l"(b));
}
__device__ __forceinline__ float2 unpk(u64 v) {
    unsigned lo, hi;
    asm("mov.b64 {%0, %1}, %2;" : "=r"(lo), "=r"(hi) : "l"(v));
    return make_float2(__uint_as_float(lo), __uint_as_float(hi));
}

// ---------------- bf16 pack/unpack (library intrinsics: mutually consistent) ----------------
__device__ __forceinline__ uint2 pack4_bf16(float4 v) {
    __nv_bfloat162 a = __float22bfloat162_rn(make_float2(v.x, v.y));
    __nv_bfloat162 b = __float22bfloat162_rn(make_float2(v.z, v.w));
    uint2 r;
    r.x = *reinterpret_cast<unsigned*>(&a);
    r.y = *reinterpret_cast<unsigned*>(&b);
    return r;
}
__device__ __forceinline__ float4 unpack4_bf16(uint2 u) {
    __nv_bfloat162 a = *reinterpret_cast<__nv_bfloat162*>(&u.x);
    __nv_bfloat162 b = *reinterpret_cast<__nv_bfloat162*>(&u.y);
    float2 fa = __bfloat1622float2(a);
    float2 fb = __bfloat1622float2(b);
    return make_float4(fa.x, fa.y, fb.x, fb.y);
}

// ---------------- preprocessing ----------------

// zero counts + transpose W (k-major, padded pitch)
__global__ void init_k(const float* __restrict__ W, int N) {
    int i = blockIdx.x * blockDim.x + threadIdx.x;
    if (i < N) g_cnt[i] = 0;
    if (i < 2 * DD * DD) {
        int l = i / (DD * DD);
        int r = i - l * DD * DD;
        int j = r / DD;
        int k = r - j * DD;
        g_Wt[l * DD * WPITCH + k * WPITCH + j] = W[i];
    }
}

// histogram; the atomic's return value is the edge's rank within its row
__global__ void count_k(const int* __restrict__ dst, int E) {
    int i = blockIdx.x * blockDim.x + threadIdx.x;
    if (i < E) g_rank[i] = atomicAdd(&g_cnt[__ldg(&dst[i])], 1);
}

// single-block exclusive scan: 1024 threads x 49 items, no cross-block sync
__global__ void __launch_bounds__(1024) scan1_k(int N, int E) {
    __shared__ int wsum[32];
    int tid = threadIdx.x, lane = tid & 31, wid = tid >> 5;
    const int PER = 49;                      // 1024*49 >= 50000
    int start = tid * PER;
    int stop = start + PER; if (stop > N) stop = N;

    int sum = 0;
    for (int i = start; i < stop; ++i) sum += g_cnt[i];

    // block inclusive scan of per-thread sums
    int x = sum;
    #pragma unroll
    for (int o = 1; o < 32; o <<= 1) {
        int t = __shfl_up_sync(0xffffffffu, x, o);
        if (lane >= o) x += t;
    }
    if (lane == 31) wsum[wid] = x;
    __syncthreads();
    if (wid == 0) {
        int s = wsum[lane];
        #pragma unroll
        for (int o = 1; o < 32; o <<= 1) {
            int t = __shfl_up_sync(0xffffffffu, s, o);
            if (lane >= o) s += t;
        }
        wsum[lane] = s;
    }
    __syncthreads();

    int run = x - sum + (wid ? wsum[wid - 1] : 0);   // exclusive prefix
    for (int i = start; i < stop; ++i) {
        int c = g_cnt[i];
        g_rowptr[i] = run;
        g_deginv[i] = 1.0f / (float)(c + 1);         // +1 self loop
        run += c;
    }
    if (tid == 0) g_rowptr[N] = E;
}

// atomic-free CSR scatter: pos = rowptr[dst] + rank
__global__ void scatter_k(const int* __restrict__ src, const int* __restrict__ dst, int E) {
    int i = blockIdx.x * blockDim.x + threadIdx.x;
    if (i < E) {
        int d = __ldg(&dst[i]);
        int pos = __ldg(&g_rowptr[d]) + g_rank[i];
        g_col[pos] = __ldg(&src[i]);
    }
}

// ---------------- GEMM: g_bufA(bf16) = x @ W[layer]^T  (packed f32x2) ----------------
// 60 rows per CTA; 250 active threads: cg = tid%25 (4 output cols), rg = tid/25
// (6 rows each). W tile (k-major) in SMEM: cg lanes read contiguous 16B ->
// conflict-free; each float4 yields two naturally-packed f32x2 column pairs.
// Input x is fp32 (feat with pitch C4, or bufB with pitch CP). Output rounded
// to bf16 once at store (accumulation fully fp32).
__global__ void __launch_bounds__(256) gemm_k(const float* __restrict__ xin, int xs4,
                                              int layer, int N) {
    __shared__ float Ws[DD * WPITCH];   // 41.6 KB
    const float* wt = g_Wt + layer * DD * WPITCH;
    for (int i = threadIdx.x; i < DD * WPITCH; i += 256) Ws[i] = wt[i];
    __syncthreads();

    int tid = threadIdx.x;
    if (tid >= 250) return;
    int cg = tid % 25;
    int rg = tid / 25;                 // 0..9
    int row0 = blockIdx.x * 60 + rg * 6;

    const float4* x4 = (const float4*)xin;
    const double2* Wd = (const double2*)Ws;   // pitch: 26 double2 per k-row

    u64 a01[6], a23[6];
    int ridx[6];
    #pragma unroll
    for (int i = 0; i < 6; ++i) {
        a01[i] = 0ull; a23[i] = 0ull;
        int r = row0 + i;
        ridx[i] = (r < N) ? r : 0;     // clamp for safe loads; store is guarded
    }

    #pragma unroll 1
    for (int k4 = 0; k4 < 25; ++k4) {
        u64 w01[4], w23[4];
        #pragma unroll
        for (int kk = 0; kk < 4; ++kk) {
            double2 t = Wd[(k4 * 4 + kk) * 26 + cg];
            w01[kk] = __double_as_longlong(t.x);
            w23[kk] = __double_as_longlong(t.y);
        }
        #pragma unroll
        for (int i = 0; i < 6; ++i) {
            float4 xv = __ldg(&x4[ridx[i] * xs4 + k4]);
            u64 d0 = dup2(xv.x), d1 = dup2(xv.y), d2 = dup2(xv.z), d3 = dup2(xv.w);
            ffma2(a01[i], d0, w01[0]); ffma2(a23[i], d0, w23[0]);
            ffma2(a01[i], d1, w01[1]); ffma2(a23[i], d1, w23[1]);
            ffma2(a01[i], d2, w01[2]); ffma2(a23[i], d2, w23[2]);
            ffma2(a01[i], d3, w01[3]); ffma2(a23[i], d3, w23[3]);
        }
    }

    #pragma unroll
    for (int i = 0; i < 6; ++i) {
        int r = row0 + i;
        if (r < N) {
            float2 lo = unpk(a01[i]);
            float2 hi = unpk(a23[i]);
            g_bufA[r * B2P + cg] = pack4_bf16(make_float4(lo.x, lo.y, hi.x, hi.y));
        }
    }
}

// ---------------- SpMM: out[r] = deg_inv[r]*(x[r] + sum_e x[col[e]]) ----------------
// One warp per row; gathers 256B-aligned bf16 rows (7 sectors/edge vs 13 fp32),
// accumulates in fp32, stores per-row normalize scale into g_sfac[layer].
// layer 0 -> fp32 out (g_bufB, GEMM1 input); layer 1 -> bf16 out (g_bufC).
__global__ void __launch_bounds__(256) spmm_k(int layer, int N) {
    int gw = (blockIdx.x * blockDim.x + threadIdx.x) >> 5;
    int lane = threadIdx.x & 31;
    if (gw >= N) return;

    bool act = lane < C4;

    float4 acc = make_float4(0.f, 0.f, 0.f, 0.f);
    if (act) acc = unpack4_bf16(__ldg(&g_bufA[gw * B2P + lane]));   // self loop

    int beg = g_rowptr[gw];
    int end = g_rowptr[gw + 1];
    for (int base = beg; base < end; base += 32) {
        int idx = base + lane;
        int c = (idx < end) ? __ldg(&g_col[idx]) : 0;
        int m = end - base; if (m > 32) m = 32;
        int j = 0;
        for (; j + 1 < m; j += 2) {
            int s0 = __shfl_sync(0xffffffffu, c, j);
            int s1 = __shfl_sync(0xffffffffu, c, j + 1);
            if (act) {
                float4 v0 = unpack4_bf16(__ldg(&g_bufA[s0 * B2P + lane]));
                float4 v1 = unpack4_bf16(__ldg(&g_bufA[s1 * B2P + lane]));
                acc.x += v0.x; acc.y += v0.y; acc.z += v0.z; acc.w += v0.w;
                acc.x += v1.x; acc.y += v1.y; acc.z += v1.z; acc.w += v1.w;
            }
        }
        if (j < m) {
            int s0 = __shfl_sync(0xffffffffu, c, j);
            if (act) {
                float4 v0 = unpack4_bf16(__ldg(&g_bufA[s0 * B2P + lane]));
                acc.x += v0.x; acc.y += v0.y; acc.z += v0.z; acc.w += v0.w;
            }
        }
    }

    float dinv = g_deginv[gw];
    acc.x *= dinv; acc.y *= dinv; acc.z *= dinv; acc.w *= dinv;

    if (act) {
        if (layer == 0) ((float4*)g_bufB)[gw * CP + lane] = acc;
        else            g_bufC[gw * B2P + lane] = pack4_bf16(acc);
    }

    float p = act ? (acc.x * acc.x + acc.y * acc.y + acc.z * acc.z + acc.w * acc.w) : 0.f;
    #pragma unroll
    for (int o = 16; o; o >>= 1) p += __shfl_xor_sync(0xffffffffu, p, o);

    if (lane == 0) g_sfac[layer * NMAX + gw] = 1.0f / fmaxf(sqrtf(p), 1e-12f);
}

// ---------------- finale: avg = (feat + s1*x1 + s2*x2) / 3 ----------------
__global__ void finale_k(const float* __restrict__ feat, float* __restrict__ avg, int N) {
    int i = blockIdx.x * blockDim.x + threadIdx.x;
    if (i >= N * C4) return;
    int row = i / C4;
    int c   = i - row * C4;
    float s1 = __ldg(&g_sfac[row]);
    float s2 = __ldg(&g_sfac[NMAX + row]);
    float4 f  = ((const float4*)feat)[i];
    float4 x1 = ((const float4*)g_bufB)[row * CP + c];
    float4 x2 = unpack4_bf16(__ldg(&g_bufC[row * B2P + c]));
    const float k = 1.0f / 3.0f;
    float4 o;
    o.x = (f.x + s1 * x1.x + s2 * x2.x) * k;
    o.y = (f.y + s1 * x1.y + s2 * x2.y) * k;
    o.z = (f.z + s1 * x1.z + s2 * x2.z) * k;
    o.w = (f.w + s1 * x1.w + s2 * x2.w) * k;
    ((float4*)avg)[i] = o;
}

// ---------------- launch ----------------

extern "C" void kernel_launch(void* const* d_in, const int* in_sizes, int n_in,
                              void* d_out, int out_size) {
    const float* feat = (const float*)d_in[0];
    const float* W    = (const float*)d_in[1];
    const int*   src  = (const int*)d_in[2];
    const int*   dst  = (const int*)d_in[3];
    float*       avg  = (float*)d_out;

    const int N = in_sizes[0] / DD;   // 50000
    const int E = in_sizes[2];        // 800000

    // lazily create side stream + events once (first call runs outside capture)
    static cudaStream_t s2 = nullptr;
    static cudaEvent_t evFork = nullptr, evJoin = nullptr;
    if (!s2) {
        cudaStreamCreateWithFlags(&s2, cudaStreamNonBlocking);
        cudaEventCreateWithFlags(&evFork, cudaEventDisableTiming);
        cudaEventCreateWithFlags(&evJoin, cudaEventDisableTiming);
    }

    void* pB; cudaGetSymbolAddress(&pB, g_bufB);

    const int gemm_blocks = (N + 59) / 60;
    const int spmm_blocks = (N * 32 + 255) / 256;

    // main chain: graph preprocessing
    init_k<<<(N + 255) / 256, 256>>>(W, N);

    // fork: layer-0 GEMM depends only on feat + g_Wt (from init_k)
    cudaEventRecord(evFork, 0);
    cudaStreamWaitEvent(s2, evFork, 0);
    gemm_k<<<gemm_blocks, 256, 0, s2>>>(feat, C4, 0, N);   // bufA = bf16(feat @ W0^T)
    cudaEventRecord(evJoin, s2);

    count_k<<<(E + 255) / 256, 256>>>(dst, E);
    scan1_k<<<1, 1024>>>(N, E);
    scatter_k<<<(E + 255) / 256, 256>>>(src, dst, E);

    // join: SpMM needs both CSR (main) and bufA (s2)
    cudaStreamWaitEvent(0, evJoin, 0);
    spmm_k<<<spmm_blocks, 256>>>(0, N);                    // bufB = x1 (fp32), sfac[0]
    gemm_k<<<gemm_blocks, 256>>>((const float*)pB, CP, 1, N); // bufA = bf16(bufB @ W1^T)
    spmm_k<<<spmm_blocks, 256>>>(1, N);                    // bufC = x2 (bf16), sfac[1]
    finale_k<<<(N * C4 + 255) / 256, 256>>>(feat, avg, N);
}

// round 9
// speedup vs baseline: 1.5410x; 1.5410x over previous
#include <cuda_runtime.h>

// Problem constants (fixed by setup_inputs: N=50000, E=800000, D=100, 2 layers)
#define NMAX 50000
#define EMAX 800000
#define DD   100
#define C4   25      // D/4 float4 chunks per dense row (feat / output)
#define CP   32      // pitched float4 chunks per internal row (512B, line-aligned)
#define WPITCH 104   // padded pitch (floats) for transposed W rows

typedef unsigned long long u64;

// ---- static device scratch (no runtime allocation allowed) ----
__device__ float g_bufA[NMAX * CP * 4];    // GEMM output / SpMM gather source (pitched)
__device__ float g_bufB[NMAX * CP * 4];    // layer-0 SpMM output x1 (pitched)
__device__ float g_Wt[2 * DD * WPITCH];    // k-major transposed weights
__device__ int   g_cnt[NMAX];              // per-row edge counts
__device__ int   g_rowptr[NMAX + 1];       // CSR row pointers
__device__ float g_deginv[NMAX];           // 1/(cnt+1)  (self loop included)
__device__ int   g_col[EMAX];              // CSR column (src) indices
__device__ int   g_rank[EMAX];             // per-edge rank within its dst row
__device__ float g_sfac[NMAX];             // layer-0 per-row 1/max(norm,eps)
__device__ int   g_agg[64];                // lookback aggregates
__device__ int   g_flag[64];               // lookback flags

// ---------------- f32x2 helpers ----------------
__device__ __forceinline__ u64 dup2(float a) {
    u64 r; unsigned ai = __float_as_uint(a);
    asm("mov.b64 %0, {%1, %1};" : "=l"(r) : "r"(ai));
    return r;
}
__device__ __forceinline__ void ffma2(u64& acc, u64 a, u64 b) {
    asm("fma.rn.f32x2 %0, %1, %2, %0;" : "+l"(acc) : "l"(a), "l"(b));
}
__device__ __forceinline__ float2 unpk(u64 v) {
    unsigned lo, hi;
    asm("mov.b64 {%0, %1}, %2;" : "=r"(lo), "=r"(hi) : "l"(v));
    return make_float2(__uint_as_float(lo), __uint_as_float(hi));
}

// ---------------- preprocessing ----------------

// zero counts + lookback flags, transpose W (k-major, padded pitch)
__global__ void init_k(const float* __restrict__ W, int N) {
    int i = blockIdx.x * blockDim.x + threadIdx.x;
    if (i < N) g_cnt[i] = 0;
    if (i < 64) { g_flag[i] = 0; g_agg[i] = 0; }
    if (i < 2 * DD * DD) {
        int l = i / (DD * DD);
        int r = i - l * DD * DD;
        int j = r / DD;
        int k = r - j * DD;
        g_Wt[l * DD * WPITCH + k * WPITCH + j] = W[i];
    }
}

// histogram; the atomic's return value is the edge's rank within its row
__global__ void count_k(const int* __restrict__ dst, int E) {
    int i = blockIdx.x * blockDim.x + threadIdx.x;
    if (i < E) g_rank[i] = atomicAdd(&g_cnt[__ldg(&dst[i])], 1);
}

// single-kernel exclusive scan with decoupled lookback (49 blocks, all resident)
__global__ void __launch_bounds__(1024) scan_lb_k(int N, int E) {
    __shared__ int wsum[32];
    __shared__ int s_prev;
    int tid = threadIdx.x, bid = blockIdx.x;
    int lane = tid & 31, wid = tid >> 5;
    int i = bid * 1024 + tid;
    int v = (i < N) ? g_cnt[i] : 0;

    int x = v;
    #pragma unroll
    for (int o = 1; o < 32; o <<= 1) {
        int t = __shfl_up_sync(0xffffffffu, x, o);
        if (lane >= o) x += t;
    }
    if (lane == 31) wsum[wid] = x;
    __syncthreads();
    if (wid == 0) {
        int s = wsum[lane];
        #pragma unroll
        for (int o = 1; o < 32; o <<= 1) {
            int t = __shfl_up_sync(0xffffffffu, s, o);
            if (lane >= o) s += t;
        }
        wsum[lane] = s;
    }
    __syncthreads();
    int excl = x - v + (wid ? wsum[wid - 1] : 0);
    int total = wsum[31];

    if (tid == 0) {
        g_agg[bid] = total;
        __threadfence();
        atomicExch(&g_flag[bid], 1);
    }
    if (wid == 0) {
        int sum = 0;
        for (int p = lane; p < bid; p += 32) {
            while (atomicAdd(&g_flag[p], 0) == 0) {}
            sum += atomicAdd(&g_agg[p], 0);
        }
        #pragma unroll
        for (int o = 16; o; o >>= 1) sum += __shfl_xor_sync(0xffffffffu, sum, o);
        if (lane == 0) s_prev = sum;
    }
    __syncthreads();
    int base = s_prev;
    if (i < N) {
        g_rowptr[i] = base + excl;
        g_deginv[i] = 1.0f / (float)(v + 1);   // +1 self loop
    }
    if (i == 0) g_rowptr[N] = E;
}

// atomic-free CSR scatter: pos = rowptr[dst] + rank
__global__ void scatter_k(const int* __restrict__ src, const int* __restrict__ dst, int E) {
    int i = blockIdx.x * blockDim.x + threadIdx.x;
    if (i < E) {
        int d = __ldg(&dst[i]);
        int pos = __ldg(&g_rowptr[d]) + g_rank[i];
        g_col[pos] = __ldg(&src[i]);
    }
}

// ---------------- GEMM: g_bufA = x @ W[layer]^T  (packed f32x2) ----------------
// 60 rows per CTA; 250 active threads: cg = tid%25 (4 output cols), rg = tid/25
// (6 rows each). W tile (k-major) in SMEM: cg lanes read contiguous 16B ->
// conflict-free; each float4 yields two naturally-packed f32x2 column pairs.
__global__ void __launch_bounds__(256) gemm_k(const float* __restrict__ xin, int xs4,
                                              int layer, int N) {
    __shared__ float Ws[DD * WPITCH];   // 41.6 KB
    const float* wt = g_Wt + layer * DD * WPITCH;
    for (int i = threadIdx.x; i < DD * WPITCH; i += 256) Ws[i] = wt[i];
    __syncthreads();

    int tid = threadIdx.x;
    if (tid >= 250) return;
    int cg = tid % 25;
    int rg = tid / 25;                 // 0..9
    int row0 = blockIdx.x * 60 + rg * 6;

    const float4* x4 = (const float4*)xin;
    const double2* Wd = (const double2*)Ws;   // pitch: 26 double2 per k-row

    u64 a01[6], a23[6];
    int ridx[6];
    #pragma unroll
    for (int i = 0; i < 6; ++i) {
        a01[i] = 0ull; a23[i] = 0ull;
        int r = row0 + i;
        ridx[i] = (r < N) ? r : 0;     // clamp for safe loads; store is guarded
    }

    #pragma unroll 1
    for (int k4 = 0; k4 < 25; ++k4) {
        u64 w01[4], w23[4];
        #pragma unroll
        for (int kk = 0; kk < 4; ++kk) {
            double2 t = Wd[(k4 * 4 + kk) * 26 + cg];
            w01[kk] = __double_as_longlong(t.x);
            w23[kk] = __double_as_longlong(t.y);
        }
        #pragma unroll
        for (int i = 0; i < 6; ++i) {
            float4 xv = __ldg(&x4[ridx[i] * xs4 + k4]);
            u64 d0 = dup2(xv.x), d1 = dup2(xv.y), d2 = dup2(xv.z), d3 = dup2(xv.w);
            ffma2(a01[i], d0, w01[0]); ffma2(a23[i], d0, w23[0]);
            ffma2(a01[i], d1, w01[1]); ffma2(a23[i], d1, w23[1]);
            ffma2(a01[i], d2, w01[2]); ffma2(a23[i], d2, w23[2]);
            ffma2(a01[i], d3, w01[3]); ffma2(a23[i], d3, w23[3]);
        }
    }

    float4* y4 = (float4*)g_bufA;   // pitched CP float4 per row
    #pragma unroll
    for (int i = 0; i < 6; ++i) {
        int r = row0 + i;
        if (r < N) {
            float2 lo = unpk(a01[i]);
            float2 hi = unpk(a23[i]);
            y4[r * CP + cg] = make_float4(lo.x, lo.y, hi.x, hi.y);
        }
    }
}

// ---------------- shared SpMM core: acc = deg_inv*(self + gathered sum) ----------------
__device__ __forceinline__ float4 spmm_row(int gw, int lane, bool act) {
    const float4* x4 = (const float4*)g_bufA;

    float4 acc = make_float4(0.f, 0.f, 0.f, 0.f);
    if (act) acc = __ldg(&x4[gw * CP + lane]);     // self loop

    int beg = g_rowptr[gw];
    int end = g_rowptr[gw + 1];
    for (int base = beg; base < end; base += 32) {
        int idx = base + lane;
        int c = (idx < end) ? __ldg(&g_col[idx]) : 0;
        int m = end - base; if (m > 32) m = 32;
        int j = 0;
        for (; j + 3 < m; j += 4) {                // 4 gathers in flight
            int s0 = __shfl_sync(0xffffffffu, c, j);
            int s1 = __shfl_sync(0xffffffffu, c, j + 1);
            int s2 = __shfl_sync(0xffffffffu, c, j + 2);
            int s3 = __shfl_sync(0xffffffffu, c, j + 3);
            if (act) {
                float4 v0 = __ldg(&x4[s0 * CP + lane]);
                float4 v1 = __ldg(&x4[s1 * CP + lane]);
                float4 v2 = __ldg(&x4[s2 * CP + lane]);
                float4 v3 = __ldg(&x4[s3 * CP + lane]);
                acc.x += v0.x + v1.x; acc.y += v0.y + v1.y;
                acc.z += v0.z + v1.z; acc.w += v0.w + v1.w;
                acc.x += v2.x + v3.x; acc.y += v2.y + v3.y;
                acc.z += v2.z + v3.z; acc.w += v2.w + v3.w;
            }
        }
        for (; j < m; ++j) {
            int s0 = __shfl_sync(0xffffffffu, c, j);
            if (act) {
                float4 v0 = __ldg(&x4[s0 * CP + lane]);
                acc.x += v0.x; acc.y += v0.y; acc.z += v0.z; acc.w += v0.w;
            }
        }
    }

    float dinv = g_deginv[gw];
    acc.x *= dinv; acc.y *= dinv; acc.z *= dinv; acc.w *= dinv;
    return acc;
}

// layer 0: store x1 (fp32) + sfac
__global__ void __launch_bounds__(256) spmm0_k(int N) {
    int gw = (blockIdx.x * blockDim.x + threadIdx.x) >> 5;
    int lane = threadIdx.x & 31;
    if (gw >= N) return;
    bool act = lane < C4;

    float4 acc = spmm_row(gw, lane, act);

    if (act) ((float4*)g_bufB)[gw * CP + lane] = acc;

    float p = act ? (acc.x * acc.x + acc.y * acc.y + acc.z * acc.z + acc.w * acc.w) : 0.f;
    #pragma unroll
    for (int o = 16; o; o >>= 1) p += __shfl_xor_sync(0xffffffffu, p, o);
    if (lane == 0) g_sfac[gw] = 1.0f / fmaxf(sqrtf(p), 1e-12f);
}

// layer 1 + fused finale: avg[r] = (feat[r] + s1*x1[r] + s2*x2[r]) / 3
__global__ void __launch_bounds__(256) spmm1_k(const float* __restrict__ feat,
                                               float* __restrict__ avg, int N) {
    int gw = (blockIdx.x * blockDim.x + threadIdx.x) >> 5;
    int lane = threadIdx.x & 31;
    if (gw >= N) return;
    bool act = lane < C4;

    float4 acc = spmm_row(gw, lane, act);   // x2 row

    float p = act ? (acc.x * acc.x + acc.y * acc.y + acc.z * acc.z + acc.w * acc.w) : 0.f;
    #pragma unroll
    for (int o = 16; o; o >>= 1) p += __shfl_xor_sync(0xffffffffu, p, o);
    float s2 = __shfl_sync(0xffffffffu,
                           (lane == 0) ? (1.0f / fmaxf(sqrtf(p), 1e-12f)) : 0.f, 0);

    if (act) {
        float s1 = __ldg(&g_sfac[gw]);
        float4 f  = ((const float4*)feat)[gw * C4 + lane];
        float4 x1 = ((const float4*)g_bufB)[gw * CP + lane];
        const float k = 1.0f / 3.0f;
        float4 o;
        o.x = (f.x + s1 * x1.x + s2 * acc.x) * k;
        o.y = (f.y + s1 * x1.y + s2 * acc.y) * k;
        o.z = (f.z + s1 * x1.z + s2 * acc.z) * k;
        o.w = (f.w + s1 * x1.w + s2 * acc.w) * k;
        ((float4*)avg)[gw * C4 + lane] = o;
    }
}

// ---------------- launch ----------------

extern "C" void kernel_launch(void* const* d_in, const int* in_sizes, int n_in,
                              void* d_out, int out_size) {
    const float* feat = (const float*)d_in[0];
    const float* W    = (const float*)d_in[1];
    const int*   src  = (const int*)d_in[2];
    const int*   dst  = (const int*)d_in[3];
    float*       avg  = (float*)d_out;

    const int N = in_sizes[0] / DD;   // 50000
    const int E = in_sizes[2];        // 800000
    const int nb = (N + 1023) / 1024; // 49 (<= 64, all resident)

    // lazily create side stream + events once (first call runs outside capture)
    static cudaStream_t s2 = nullptr;
    static cudaEvent_t evFork = nullptr, evJoin = nullptr;
    if (!s2) {
        cudaStreamCreateWithFlags(&s2, cudaStreamNonBlocking);
        cudaEventCreateWithFlags(&evFork, cudaEventDisableTiming);
        cudaEventCreateWithFlags(&evJoin, cudaEventDisableTiming);
    }

    void* pB; cudaGetSymbolAddress(&pB, g_bufB);

    const int gemm_blocks = (N + 59) / 60;
    const int spmm_blocks = (N * 32 + 255) / 256;

    // main chain: graph preprocessing
    init_k<<<(N + 255) / 256, 256>>>(W, N);

    // fork: layer-0 GEMM depends only on feat + g_Wt (from init_k)
    cudaEventRecord(evFork, 0);
    cudaStreamWaitEvent(s2, evFork, 0);
    gemm_k<<<gemm_blocks, 256, 0, s2>>>(feat, C4, 0, N);   // bufA = feat @ W0^T
    cudaEventRecord(evJoin, s2);

    count_k<<<(E + 255) / 256, 256>>>(dst, E);
    scan_lb_k<<<nb, 1024>>>(N, E);
    scatter_k<<<(E + 255) / 256, 256>>>(src, dst, E);

    // join: SpMM needs both CSR (main) and bufA (s2)
    cudaStreamWaitEvent(0, evJoin, 0);
    spmm0_k<<<spmm_blocks, 256>>>(N);                        // bufB = x1, sfac
    gemm_k<<<gemm_blocks, 256>>>((const float*)pB, CP, 1, N); // bufA = bufB @ W1^T
    spmm1_k<<<spmm_blocks, 256>>>(feat, avg, N);             // avg (fused finale)
}